// round 14
// baseline (speedup 1.0000x reference)
#include <cuda_runtime.h>
#include <cuda_bf16.h>

// text [SEQ=200, BATCH=4096] int32 (row-major text[s*BATCH+b]),
// w [V=50000] f32, bias [1] f32.  out[b] = sum_{unique t in doc b} w[t] + bias.
//
// R14: WARP-PER-DOC. R11-R13 showed the block-wide barrier convoy (8 warps x
// 5-6 syncs) is the governing cost and phase-merging doesn't fix it. Now the
// only block barrier is after the cooperative coalesced text load; each warp
// then owns one doc end-to-end with __syncwarp-separated race phases (~23cyc,
// no HW barrier slot, no cross-warp convoy) and a pure warp-shuffle reduction.
// Tables are UNINITIALIZED + self-validating (accept claimed index m only if
// m<SEQ && toks[doc][m]==token; then m is provably in the same token group ->
// exactly-once). Same-token items are same-warp, so post-syncwarp reads are
// consistent. Cascade A(2048)->B(512)->C(512)->exact scan (~0.3% of docs).

#define SEQ    200
#define BATCH  4096
#define DOCS   4
#define NTHR   128
#define NITEM  (SEQ * DOCS)       // 800
#define KIT    7                  // ceil(SEQ/32) items per lane
#define ABITS  11
#define BBITS  9
#define CBITS  9
#define ASZ    (1 << ABITS)       // 2048 u8/doc (uninitialized)
#define BSZ    (1 << BBITS)       // 512
#define CSZ    (1 << CBITS)       // 512

__global__ __launch_bounds__(NTHR, 12)
void MNB_24111946400019_kernel(const int* __restrict__ text,
                               const float* __restrict__ w,
                               const float* __restrict__ bias,
                               float* __restrict__ out)
{
    __shared__ int           toks[DOCS * SEQ];     // 3.2KB
    __shared__ unsigned char tabA[DOCS * ASZ];     // 8KB (uninit, self-validating)
    __shared__ unsigned char tabB[DOCS * BSZ];     // 2KB (uninit)
    __shared__ unsigned char tabC[DOCS * CSZ];     // 2KB (uninit)

    const int b0  = blockIdx.x * DOCS;
    const int tid = threadIdx.x;

    // ── Phase 0 (block): coalesced text load, i=s*4+d (16B per 4 lanes) ──
    #pragma unroll
    for (int k = 0; k < KIT; ++k) {
        const int i = tid + k * NTHR;
        if (i < NITEM)
            toks[(i & 3) * SEQ + (i >> 2)] = __ldg(&text[(i >> 2) * BATCH + b0 + (i & 3)]);
    }
    __syncthreads();                               // the ONLY block barrier

    // ── Warp-local: warp wd owns doc wd ──
    const int wd   = tid >> 5;
    const int lane = tid & 31;
    const int dt   = wd * SEQ;

    int      tt[KIT];
    float    wv[KIT];
    unsigned hh[KIT];
    int      st[KIT];

    #pragma unroll
    for (int k = 0; k < KIT; ++k) {
        const int j = lane + k * 32;
        tt[k] = (j < SEQ) ? toks[dt + j] : 0;
    }
    #pragma unroll
    for (int k = 0; k < KIT; ++k) wv[k] = __ldg(&w[tt[k]]);   // latency hides below

    // Level 1 race: store claimed seq index (byte) at h1(t).
    #pragma unroll
    for (int k = 0; k < KIT; ++k) {
        const int j = lane + k * 32;
        hh[k] = ((unsigned)tt[k] * 2654435761u) >> (32 - ABITS);
        if (j < SEQ) tabA[wd * ASZ + hh[k]] = (unsigned char)j;
    }
    __syncwarp();

    // Verify A; unresolved store B and C (disjoint) simultaneously.
    #pragma unroll
    for (int k = 0; k < KIT; ++k) {
        st[k] = 0;
        const int j = lane + k * 32;
        if (j < SEQ) {
            const int m = tabA[wd * ASZ + hh[k]];
            if (m < SEQ && toks[dt + m] == tt[k]) {
                st[k] = (m == j) ? 1 : 0;          // verified claimant / duplicate
            } else {
                st[k] = 2;                          // ~10 items/doc
                const unsigned hb = ((unsigned)tt[k] * 0x85EBCA77u) >> (32 - BBITS);
                const unsigned hc = ((unsigned)tt[k] * 0xC2B2AE3Du) >> (32 - CBITS);
                tabB[wd * BSZ + hb] = (unsigned char)j;
                tabC[wd * CSZ + hc] = (unsigned char)j;
            }
        }
    }
    __syncwarp();

    // Resolve B -> C -> exact scan; accumulate.
    float v = 0.0f;
    #pragma unroll
    for (int k = 0; k < KIT; ++k) {
        int c = st[k];
        if (c == 2) {
            const int j = lane + k * 32;
            const unsigned hb = ((unsigned)tt[k] * 0x85EBCA77u) >> (32 - BBITS);
            int m = tabB[wd * BSZ + hb];
            if (m < SEQ && toks[dt + m] == tt[k]) {
                c = (m == j) ? 1 : 0;
            } else {
                const unsigned hc = ((unsigned)tt[k] * 0xC2B2AE3Du) >> (32 - CBITS);
                m = tabC[wd * CSZ + hc];
                if (m < SEQ && toks[dt + m] == tt[k]) {
                    c = (m == j) ? 1 : 0;
                } else {
                    // Exact first-occurrence scan (~0.3% of docs, one item).
                    int f = 0;
                    while (toks[dt + f] != tt[k]) ++f;   // terminates at f==j
                    c = (f == j) ? 1 : 0;
                }
            }
        }
        if (c == 1) v += wv[k];
    }

    // ── Warp reduction; lane 0 writes the doc's output ──
    v += __shfl_xor_sync(0xffffffffu, v, 16);
    v += __shfl_xor_sync(0xffffffffu, v, 8);
    v += __shfl_xor_sync(0xffffffffu, v, 4);
    v += __shfl_xor_sync(0xffffffffu, v, 2);
    v += __shfl_xor_sync(0xffffffffu, v, 1);
    if (lane == 0) out[b0 + wd] = v + bias[0];
}

extern "C" void kernel_launch(void* const* d_in, const int* in_sizes, int n_in,
                              void* d_out, int out_size)
{
    const int*   text = (const int*)d_in[0];
    const float* w    = (const float*)d_in[1];
    const float* bias = (const float*)d_in[2];
    float*       out  = (float*)d_out;

    MNB_24111946400019_kernel<<<BATCH / DOCS, NTHR>>>(text, w, bias, out);
}

// round 15
// speedup vs baseline: 1.1910x; 1.1910x over previous
#include <cuda_runtime.h>
#include <cuda_bf16.h>

// text [SEQ=200, BATCH=4096] int32 (row-major text[s*BATCH+b]),
// w [V=50000] f32, bias [1] f32.  out[b] = sum_{unique t in doc b} w[t] + bias.
//
// R15 = R9's exact phase structure (the measured local optimum: 6 uniform
// block-wide syncs, single reused 2048-slot/doc byte table, speculative
// gathers, DOCS=4 / NTHR=256 / grid 1024) with ONE delta: per-thread items
// regrouped from (4 seqs x 1 doc) to (1 seq x 4 docs), so thread tid<200
// loads its 4 tokens with a single aligned int4 (800 guarded LDG.32 ->
// 200 LDG.128, no per-item bounds checks), and the 224 dummy w[0] gather
// lanes R9 paid per block are predicated away.

#define SEQ    200
#define BATCH  4096
#define DOCS   4
#define NTHR   256
#define HBITS  11
#define HSIZE  (1 << HBITS)       // 2048 byte slots per doc, reused across levels

__global__ __launch_bounds__(NTHR, 7)
void MNB_24111946400019_kernel(const int* __restrict__ text,
                               const float* __restrict__ w,
                               const float* __restrict__ bias,
                               float* __restrict__ out)
{
    __shared__ int           toks[DOCS * SEQ];          // 3.2KB, [doc][seq]
    __shared__ unsigned char marker[DOCS * HSIZE];      // 8KB, reused L1/L2/L3
    __shared__ float         part[DOCS][9];

    const int b0  = blockIdx.x * DOCS;
    const int tid = threadIdx.x;
    const bool act = (tid < SEQ);

    int   tt[4];
    float wv[4];
    int   st[4];

    // ── Phase 0: one int4 text load per active thread (seq=tid, docs 0..3),
    //    speculative gathers fire immediately; marker init is the filler. ──
    if (act) {
        const int4 tx = *reinterpret_cast<const int4*>(text + tid * BATCH + b0);
        tt[0] = tx.x; tt[1] = tx.y; tt[2] = tx.z; tt[3] = tx.w;
    } else {
        tt[0] = tt[1] = tt[2] = tt[3] = 0;
    }
    #pragma unroll
    for (int k = 0; k < 4; ++k) wv[k] = act ? __ldg(&w[tt[k]]) : 0.0f;  // in flight
    {
        int4* m4 = reinterpret_cast<int4*>(marker);
        const int4 ff = make_int4(-1, -1, -1, -1);
        m4[tid]        = ff;                             // 8KB filler work
        m4[tid + NTHR] = ff;
    }
    if (act) {
        #pragma unroll
        for (int k = 0; k < 4; ++k) toks[k * SEQ + tid] = tt[k];
    }
    __syncthreads();

    // ── Phase 1: level-1 racing byte store ──
    if (act) {
        #pragma unroll
        for (int k = 0; k < 4; ++k) {
            const unsigned h1 = ((unsigned)tt[k] * 2654435761u) >> (32 - HBITS);
            marker[k * HSIZE + h1] = (unsigned char)tid;
        }
    }
    __syncthreads();

    // ── Phase 2: read level 1 (genuine same-phase racer), classify ──
    #pragma unroll
    for (int k = 0; k < 4; ++k) {
        st[k] = 0;
        if (act) {
            const unsigned h1 = ((unsigned)tt[k] * 2654435761u) >> (32 - HBITS);
            const int m = marker[k * HSIZE + h1];
            if (toks[k * SEQ + m] == tt[k]) st[k] = (m == tid) ? 1 : 0;
            else                            st[k] = 2;          // ~10/doc
        }
    }
    __syncthreads();                     // level-1 reads before level-2 stores

    // ── Phase 3: level-2 store (same table, h2) ──
    #pragma unroll
    for (int k = 0; k < 4; ++k) {
        if (st[k] == 2) {
            const unsigned h2 = ((unsigned)tt[k] * 0x85EBCA77u) >> (32 - HBITS);
            marker[k * HSIZE + h2] = (unsigned char)tid;
        }
    }
    __syncthreads();

    // ── Phase 4: read level 2; leftovers store level 3 (h3) ──
    #pragma unroll
    for (int k = 0; k < 4; ++k) {
        if (st[k] == 2) {
            const unsigned h2 = ((unsigned)tt[k] * 0x85EBCA77u) >> (32 - HBITS);
            const int m = marker[k * HSIZE + h2];
            if (toks[k * SEQ + m] == tt[k]) st[k] = (m == tid) ? 1 : 0;
            else                            st[k] = 3;          // ~0.02/doc
        }
    }
    __syncthreads();
    #pragma unroll
    for (int k = 0; k < 4; ++k) {
        if (st[k] == 3) {
            const unsigned h3 = ((unsigned)tt[k] * 0xC2B2AE3Du) >> (32 - HBITS);
            marker[k * HSIZE + h3] = (unsigned char)tid;
        }
    }
    __syncthreads();

    // ── Phase 5: resolve level 3 / exact scan; accumulate per-doc ──
    float v[4];
    #pragma unroll
    for (int k = 0; k < 4; ++k) {
        int c = st[k];
        if (c == 3) {
            const unsigned h3 = ((unsigned)tt[k] * 0xC2B2AE3Du) >> (32 - HBITS);
            const int m = marker[k * HSIZE + h3];
            if (toks[k * SEQ + m] == tt[k]) {
                c = (m == tid) ? 1 : 0;
            } else {
                // Exact first-occurrence scan (~1e-5/doc), 2-way MLP.
                int f = -1;
                for (int j = 0; j < SEQ; j += 2) {
                    const int a0 = toks[k * SEQ + j];
                    const int a1 = toks[k * SEQ + j + 1];
                    if (a0 == tt[k])              { f = j;     break; }
                    if (j + 1 < SEQ && a1 == tt[k]) { f = j + 1; break; }
                }
                c = (f == tid) ? 1 : 0;
            }
        }
        v[k] = (c == 1) ? wv[k] : 0.0f;
    }

    // ── Reduction: 4 independent warp reductions, then 32-thread finish ──
    #pragma unroll
    for (int k = 0; k < 4; ++k) {
        float s = v[k];
        s += __shfl_xor_sync(0xffffffffu, s, 16);
        s += __shfl_xor_sync(0xffffffffu, s, 8);
        s += __shfl_xor_sync(0xffffffffu, s, 4);
        s += __shfl_xor_sync(0xffffffffu, s, 2);
        s += __shfl_xor_sync(0xffffffffu, s, 1);
        if ((tid & 31) == 0) part[k][tid >> 5] = s;
    }
    __syncthreads();

    if (tid < 32) {
        const int dd = tid >> 3;                         // doc 0..3
        const int j  = tid & 7;                          // warp slot
        float s = part[dd][j];
        s += __shfl_xor_sync(0xffffffffu, s, 4);
        s += __shfl_xor_sync(0xffffffffu, s, 2);
        s += __shfl_xor_sync(0xffffffffu, s, 1);
        if (j == 0) out[b0 + dd] = s + bias[0];
    }
}

extern "C" void kernel_launch(void* const* d_in, const int* in_sizes, int n_in,
                              void* d_out, int out_size)
{
    const int*   text = (const int*)d_in[0];
    const float* w    = (const float*)d_in[1];
    const float* bias = (const float*)d_in[2];
    float*       out  = (float*)d_out;

    MNB_24111946400019_kernel<<<BATCH / DOCS, NTHR>>>(text, w, bias, out);
}